// round 5
// baseline (speedup 1.0000x reference)
#include <cuda_runtime.h>

// Problem constants (fixed by reference setup_inputs)
#define BROWS 16384
#define DCOLS 512
#define D4    (DCOLS / 4)            // 128 float4 per row
#define THREADS_PER_ROW 128          // one float4 per thread covers a row
#define ROWS_PER_BLOCK 2
#define THREADS_PER_BLOCK (THREADS_PER_ROW * ROWS_PER_BLOCK)   // 256
#define NBLOCKS (BROWS / ROWS_PER_BLOCK)                        // 8192
#define WARPS_PER_BLOCK (THREADS_PER_BLOCK / 32)                // 8
#define INV_T 10.0f                  // 1 / TEMPERATURE

// Scratch for deterministic single-kernel reduction (no cudaMalloc allowed)
__device__ float g_partial[NBLOCKS];
__device__ unsigned int g_count;     // zero-initialized; last block resets it

__global__ __launch_bounds__(THREADS_PER_BLOCK)
void contrastive_fused_kernel(const float4* __restrict__ shared_i,
                              const float4* __restrict__ specific_i,
                              const float4* __restrict__ shared_j,
                              const float4* __restrict__ specific_j,
                              float* __restrict__ out) {
    const int tid   = threadIdx.x;
    const int warp  = tid >> 5;                  // 0..7
    const int lane  = tid & 31;
    const int rloc  = tid >> 7;                  // row within block: 0 or 1
    const int chunk = tid & (THREADS_PER_ROW - 1);  // float4 index within row
    const int row   = blockIdx.x * ROWS_PER_BLOCK + rloc;

    const size_t idx = (size_t)row * D4 + chunk;

    // 4 independent LDG.128 — front-batched, no loop-carried deps.
    const float4 a = __ldg(&shared_i[idx]);
    const float4 b = __ldg(&specific_i[idx]);
    const float4 c = __ldg(&shared_j[idx]);
    const float4 d = __ldg(&specific_j[idx]);

    float s_ss, s_sp, s_ps, s_pp;
    s_ss = a.x * c.x; s_ss = fmaf(a.y, c.y, s_ss);
    s_ss = fmaf(a.z, c.z, s_ss); s_ss = fmaf(a.w, c.w, s_ss);

    s_sp = a.x * d.x; s_sp = fmaf(a.y, d.y, s_sp);
    s_sp = fmaf(a.z, d.z, s_sp); s_sp = fmaf(a.w, d.w, s_sp);

    s_ps = b.x * c.x; s_ps = fmaf(b.y, c.y, s_ps);
    s_ps = fmaf(b.z, c.z, s_ps); s_ps = fmaf(b.w, c.w, s_ps);

    s_pp = b.x * d.x; s_pp = fmaf(b.y, d.y, s_pp);
    s_pp = fmaf(b.z, d.z, s_pp); s_pp = fmaf(b.w, d.w, s_pp);

    // Warp reduction (each warp covers 32 consecutive chunks of one row)
    #pragma unroll
    for (int off = 16; off > 0; off >>= 1) {
        s_ss += __shfl_down_sync(0xffffffffu, s_ss, off);
        s_sp += __shfl_down_sync(0xffffffffu, s_sp, off);
        s_ps += __shfl_down_sync(0xffffffffu, s_ps, off);
        s_pp += __shfl_down_sync(0xffffffffu, s_pp, off);
    }

    // Per-warp partials: sh[warp][0..3]
    __shared__ float sh[WARPS_PER_BLOCK][4];
    if (lane == 0) {
        sh[warp][0] = s_ss;
        sh[warp][1] = s_sp;
        sh[warp][2] = s_ps;
        sh[warp][3] = s_pp;
    }
    __syncthreads();

    // One thread per row combines its 4 warps and computes the row loss.
    __shared__ float sh_loss[ROWS_PER_BLOCK];
    if (chunk == 0) {                            // tid == 0 and tid == 128
        const int wbase = rloc * 4;              // warps 0-3 row0, 4-7 row1
        float t0 = sh[wbase][0] + sh[wbase + 1][0] + sh[wbase + 2][0] + sh[wbase + 3][0];
        float t1 = sh[wbase][1] + sh[wbase + 1][1] + sh[wbase + 2][1] + sh[wbase + 3][1];
        float t2 = sh[wbase][2] + sh[wbase + 1][2] + sh[wbase + 2][2] + sh[wbase + 3][2];
        float t3 = sh[wbase][3] + sh[wbase + 1][3] + sh[wbase + 2][3] + sh[wbase + 3][3];
        const float l0 = t0 * INV_T;
        const float l1 = t1 * INV_T;
        const float l2 = t2 * INV_T;
        const float l3 = t3 * INV_T;
        const float m  = fmaxf(fmaxf(l0, l1), fmaxf(l2, l3));
        const float lse = m + logf(expf(l0 - m) + expf(l1 - m) +
                                   expf(l2 - m) + expf(l3 - m));
        sh_loss[rloc] = lse - l0;                // -(log_softmax[0])
    }
    __syncthreads();

    __shared__ bool is_last;
    if (tid == 0) {
        g_partial[blockIdx.x] = sh_loss[0] + sh_loss[1];
        __threadfence();                         // make partial visible
        unsigned int t = atomicAdd(&g_count, 1u);
        is_last = (t == NBLOCKS - 1u);
    }
    __syncthreads();

    // Last block: deterministic final reduction (fixed order + shuffle tree).
    if (is_last) {
        __threadfence();                         // acquire all partials
        float v = 0.f;
        #pragma unroll
        for (int k = 0; k < NBLOCKS / THREADS_PER_BLOCK; ++k)   // 32 each
            v += g_partial[tid + k * THREADS_PER_BLOCK];

        #pragma unroll
        for (int off = 16; off > 0; off >>= 1)
            v += __shfl_down_sync(0xffffffffu, v, off);

        __shared__ float shf[WARPS_PER_BLOCK];
        if (lane == 0) shf[warp] = v;
        __syncthreads();

        if (warp == 0) {
            float w = (lane < WARPS_PER_BLOCK) ? shf[lane] : 0.f;
            #pragma unroll
            for (int off = WARPS_PER_BLOCK / 2; off > 0; off >>= 1)
                w += __shfl_down_sync(0xffffffffu, w, off);
            if (lane == 0) {
                out[0] = w / (float)BROWS;
                g_count = 0;                     // reset for next graph replay
            }
        }
    }
}

extern "C" void kernel_launch(void* const* d_in, const int* in_sizes, int n_in,
                              void* d_out, int out_size) {
    const float4* shared_i   = (const float4*)d_in[0];
    const float4* specific_i = (const float4*)d_in[1];
    const float4* shared_j   = (const float4*)d_in[2];
    const float4* specific_j = (const float4*)d_in[3];
    float* out = (float*)d_out;

    contrastive_fused_kernel<<<NBLOCKS, THREADS_PER_BLOCK>>>(
        shared_i, specific_i, shared_j, specific_j, out);
}